// round 5
// baseline (speedup 1.0000x reference)
#include <cuda_runtime.h>
#include <cuda_bf16.h>

// XingLoss: P=16384 rows, N=1024 points (x,y) fp32. segn = N/4 = 256 segments/row.
// Segment i of row p uses points x[p, 3i .. 3i+3]; term depends on
//   c12 = cross(v1,v2)  (sign only -> direct),  sina = cross(v1,v3)/(|v1||v3|)
// out = scale * mean_p( sum_i term / segn )
//
// Single fused kernel: per-row block partials + deterministic last-block-done
// final reduction (counter reset each launch -> graph-replay safe).

#define P_ROWS 16384
#define SEGN   256
#define NPTS   1024

__device__ float g_partials[P_ROWS];
__device__ unsigned int g_counter;  // static-zero; last block resets to 0 every launch

// Decode a scalar of unknown dtype (int32 or fp32). For a plain python int
// (e.g. 1), the raw bits reinterpreted as float are denormal/huge -> use int.
__device__ __forceinline__ float decode_scale(const int* sp) {
    if (sp == nullptr) return 1.0f;
    int bits = *sp;
    float f = __int_as_float(bits);
    float af = fabsf(f);
    if (af > 1e-30f && af < 1e30f) return f;   // plausible float
    return (float)bits;                        // treat as int
}

__global__ __launch_bounds__(SEGN) void xing_fused_kernel(const float* __restrict__ x,
                                                          const int* __restrict__ scale_p,
                                                          float* __restrict__ out) {
    const int p = blockIdx.x;
    const int i = threadIdx.x;  // segment index within row
    const int lane = i & 31, wid = i >> 5;

    // float offset of point (p, 3i): 8B-aligned float2 loads
    const float* base = x + (size_t)p * (NPTS * 2) + 6 * i;

    float2 q0 = *reinterpret_cast<const float2*>(base + 0);
    float2 q1 = *reinterpret_cast<const float2*>(base + 2);
    float2 q2 = *reinterpret_cast<const float2*>(base + 4);
    float2 q3 = *reinterpret_cast<const float2*>(base + 6);

    float v1x = q1.x - q0.x, v1y = q1.y - q0.y;
    float v2x = q2.x - q1.x, v2y = q2.y - q1.y;
    float v3x = q3.x - q2.x, v3y = q3.y - q2.y;

    float c12 = v1x * v2y - v1y * v2x;
    float c13 = v1x * v3y - v1y * v3x;
    float d1 = v1x * v1x + v1y * v1y;
    float d3 = v3x * v3x + v3y * v3y;
    float sina = c13 / sqrtf(d1 * d3);

    // direct = (s12 >= 0); sign(s12) == sign(c12) since norms > 0
    float term = (c12 >= 0.0f) ? fmaxf(-sina, 0.0f) : fmaxf(sina, 0.0f);

    // warp reduce
    #pragma unroll
    for (int off = 16; off > 0; off >>= 1)
        term += __shfl_down_sync(0xFFFFFFFFu, term, off);

    __shared__ float warp_sums[SEGN / 32];
    __shared__ int is_last;
    if (lane == 0) warp_sums[wid] = term;
    __syncthreads();

    if (wid == 0) {
        float s = (lane < SEGN / 32) ? warp_sums[lane] : 0.0f;
        #pragma unroll
        for (int off = 4; off > 0; off >>= 1)
            s += __shfl_down_sync(0xFFFFFFFFu, s, off);
        if (lane == 0) {
            g_partials[p] = s;
            __threadfence();  // make partial visible before signaling
            unsigned int prev = atomicAdd(&g_counter, 1u);
            is_last = (prev == (unsigned int)(P_ROWS - 1)) ? 1 : 0;
        }
    }
    __syncthreads();

    if (is_last) {
        // This block runs after all partials are globally visible.
        // 16384 floats / 256 threads = 64 independent L2 loads per thread.
        float a = 0.0f;
        #pragma unroll 8
        for (int j = i; j < P_ROWS; j += SEGN)
            a += __ldcg(&g_partials[j]);

        #pragma unroll
        for (int off = 16; off > 0; off >>= 1)
            a += __shfl_down_sync(0xFFFFFFFFu, a, off);

        if (lane == 0) warp_sums[wid] = a;
        __syncthreads();

        if (wid == 0) {
            float s = (lane < SEGN / 32) ? warp_sums[lane] : 0.0f;
            #pragma unroll
            for (int off = 4; off > 0; off >>= 1)
                s += __shfl_down_sync(0xFFFFFFFFu, s, off);
            if (lane == 0) {
                float scale = decode_scale(scale_p);
                // mean over P of (row_sum / SEGN), times scale
                out[0] = s * (scale / ((float)SEGN * (float)P_ROWS));
                g_counter = 0;  // reset for next graph replay
            }
        }
    }
}

extern "C" void kernel_launch(void* const* d_in, const int* in_sizes, int n_in,
                              void* d_out, int out_size) {
    const float* x = (const float*)d_in[0];
    const int* scale_p = (n_in > 1) ? (const int*)d_in[1] : nullptr;
    float* out = (float*)d_out;

    xing_fused_kernel<<<P_ROWS, SEGN>>>(x, scale_p, out);
}

// round 6
// speedup vs baseline: 2.5598x; 2.5598x over previous
#include <cuda_runtime.h>
#include <cuda_bf16.h>

// XingLoss: P=16384 rows, N=1024 points (x,y) fp32. segn = N/4 = 256 segments/row.
// Segment i of row p uses points x[p, 3i .. 3i+3]:
//   c12 = cross(v1,v2) (sign only), sina = cross(v1,v3)/(|v1||v3|)
//   term = c12>=0 ? relu(-sina) : relu(sina)
// out = scale * sum_all_terms / (P * segn)   (mean over rows of row_sum/segn)
//
// Fat-block fused kernel: grid=1024, each block owns 16 rows (16 seg/thread).
// Deterministic last-block-done final reduction over 1024 partials.
// Fence+atomic run once per block (1024 total) -> negligible, unlike R4's 16384.

#define P_ROWS        16384
#define SEGN          256
#define NPTS          1024
#define ROWS_PER_BLK  16
#define GRID_BLKS     (P_ROWS / ROWS_PER_BLK)   // 1024

__device__ float g_partials[GRID_BLKS];
__device__ unsigned int g_counter;  // static-zero; last block resets each launch

// Decode a scalar of unknown dtype (int32 or fp32).
__device__ __forceinline__ float decode_scale(const int* sp) {
    if (sp == nullptr) return 1.0f;
    int bits = *sp;
    float f = __int_as_float(bits);
    float af = fabsf(f);
    if (af > 1e-30f && af < 1e30f) return f;
    return (float)bits;
}

__device__ __forceinline__ float seg_term(const float* __restrict__ base) {
    float2 q0 = *reinterpret_cast<const float2*>(base + 0);
    float2 q1 = *reinterpret_cast<const float2*>(base + 2);
    float2 q2 = *reinterpret_cast<const float2*>(base + 4);
    float2 q3 = *reinterpret_cast<const float2*>(base + 6);

    float v1x = q1.x - q0.x, v1y = q1.y - q0.y;
    float v2x = q2.x - q1.x, v2y = q2.y - q1.y;
    float v3x = q3.x - q2.x, v3y = q3.y - q2.y;

    float c12 = v1x * v2y - v1y * v2x;
    float c13 = v1x * v3y - v1y * v3x;
    float d1 = v1x * v1x + v1y * v1y;
    float d3 = v3x * v3x + v3y * v3y;
    float sina = c13 / sqrtf(d1 * d3);

    return (c12 >= 0.0f) ? fmaxf(-sina, 0.0f) : fmaxf(sina, 0.0f);
}

__global__ __launch_bounds__(SEGN) void xing_fused_kernel(const float* __restrict__ x,
                                                          const int* __restrict__ scale_p,
                                                          float* __restrict__ out) {
    const int t = threadIdx.x;          // segment index within each row
    const int lane = t & 31, wid = t >> 5;
    const int row0 = blockIdx.x * ROWS_PER_BLK;

    // Thread t handles segment t of each of the block's 16 rows.
    const float* base = x + (size_t)row0 * (NPTS * 2) + 6 * t;

    float acc = 0.0f;
    #pragma unroll 2
    for (int r = 0; r < ROWS_PER_BLK; r++)
        acc += seg_term(base + (size_t)r * (NPTS * 2));

    // warp reduce
    #pragma unroll
    for (int off = 16; off > 0; off >>= 1)
        acc += __shfl_down_sync(0xFFFFFFFFu, acc, off);

    __shared__ float warp_sums[SEGN / 32];
    __shared__ int is_last;
    if (lane == 0) warp_sums[wid] = acc;
    __syncthreads();

    if (wid == 0) {
        float s = (lane < SEGN / 32) ? warp_sums[lane] : 0.0f;
        #pragma unroll
        for (int off = 4; off > 0; off >>= 1)
            s += __shfl_down_sync(0xFFFFFFFFu, s, off);
        if (lane == 0) {
            g_partials[blockIdx.x] = s;
            __threadfence();  // once per block (1024 total) -> cheap
            unsigned int prev = atomicAdd(&g_counter, 1u);
            is_last = (prev == (unsigned int)(GRID_BLKS - 1)) ? 1 : 0;
        }
    }
    __syncthreads();

    if (is_last) {
        // 1024 partials / 256 threads = 4 loads each; L2/DRAM latency overlapped.
        float a = 0.0f;
        #pragma unroll
        for (int j = 0; j < GRID_BLKS / SEGN; j++)
            a += __ldcg(&g_partials[t + j * SEGN]);

        #pragma unroll
        for (int off = 16; off > 0; off >>= 1)
            a += __shfl_down_sync(0xFFFFFFFFu, a, off);

        if (lane == 0) warp_sums[wid] = a;
        __syncthreads();

        if (wid == 0) {
            float s = (lane < SEGN / 32) ? warp_sums[lane] : 0.0f;
            #pragma unroll
            for (int off = 4; off > 0; off >>= 1)
                s += __shfl_down_sync(0xFFFFFFFFu, s, off);
            if (lane == 0) {
                float scale = decode_scale(scale_p);
                out[0] = s * (scale / ((float)SEGN * (float)P_ROWS));
                g_counter = 0;  // reset for next graph replay
            }
        }
    }
}

extern "C" void kernel_launch(void* const* d_in, const int* in_sizes, int n_in,
                              void* d_out, int out_size) {
    const float* x = (const float*)d_in[0];
    const int* scale_p = (n_in > 1) ? (const int*)d_in[1] : nullptr;
    float* out = (float*)d_out;

    xing_fused_kernel<<<GRID_BLKS, SEGN>>>(x, scale_p, out);
}

// round 8
// speedup vs baseline: 3.1226x; 1.2199x over previous
#include <cuda_runtime.h>
#include <cuda_bf16.h>

// XingLoss: P=16384 rows, N=1024 points (x,y) fp32. segn = N/4 = 256 segments/row.
// Segment i of row p uses points x[p, 3i .. 3i+3]:
//   c12 = cross(v1,v2) (sign only), c13 = cross(v1,v3)
//   term = (c12>=0 ? relu(-c13) : relu(c13)) * rsqrt(|v1|^2 * |v3|^2)
// out = scale * sum_all_terms / (P * segn)
//
// Each thread handles 2 adjacent segments via 4x LDG.128 (floats [12t..12t+15],
// 48t bytes -> 16B aligned). Block = 256 thr = 2 rows x 128 thr, 8 iterations
// -> 16 rows/block, grid = 1024. Last-block-done final reduction.

#define P_ROWS        16384
#define SEGN          256
#define NPTS          1024
#define ROWS_PER_BLK  16
#define GRID_BLKS     (P_ROWS / ROWS_PER_BLK)   // 1024

__device__ float g_partials[GRID_BLKS];
__device__ unsigned int g_counter;  // static-zero; last block resets each launch

// Decode a scalar of unknown dtype (int32 or fp32).
__device__ __forceinline__ float decode_scale(const int* sp) {
    if (sp == nullptr) return 1.0f;
    int bits = *sp;
    float f = __int_as_float(bits);
    float af = fabsf(f);
    if (af > 1e-30f && af < 1e30f) return f;
    return (float)bits;
}

// One segment: points q0..q3 as 8 consecutive floats f[0..7].
__device__ __forceinline__ float seg_term8(const float* f) {
    float v1x = f[2] - f[0], v1y = f[3] - f[1];
    float v2x = f[4] - f[2], v2y = f[5] - f[3];
    float v3x = f[6] - f[4], v3y = f[7] - f[5];

    float c12 = v1x * v2y - v1y * v2x;
    float c13 = v1x * v3y - v1y * v3x;
    float d1  = v1x * v1x + v1y * v1y;
    float d3  = v3x * v3x + v3y * v3y;

    float sel = (c12 >= 0.0f) ? fmaxf(-c13, 0.0f) : fmaxf(c13, 0.0f);
    return sel * rsqrtf(d1 * d3);
}

__global__ __launch_bounds__(256) void xing_fused_kernel(const float* __restrict__ x,
                                                         const int* __restrict__ scale_p,
                                                         float* __restrict__ out) {
    const int t    = threadIdx.x;
    const int lane = t & 31, wid = t >> 5;
    const int tl   = t & 127;          // thread within row (handles segs 2tl, 2tl+1)
    const int rsub = t >> 7;           // 0/1: which row of the pair
    const int row0 = blockIdx.x * ROWS_PER_BLK;

    // floats [12*tl .. 12*tl+15] of each assigned row; 48*tl bytes -> 16B aligned
    const float4* base = reinterpret_cast<const float4*>(
        x + (size_t)(row0 + rsub) * (NPTS * 2) + 12 * tl);

    float acc = 0.0f;
    #pragma unroll 2
    for (int it = 0; it < ROWS_PER_BLK / 2; it++) {
        const float4* bp = base + (size_t)it * (2 * NPTS * 2 / 4);  // +2 rows per iter
        float4 r0 = bp[0];
        float4 r1 = bp[1];
        float4 r2 = bp[2];
        float4 r3 = bp[3];

        float f[14];
        f[0]=r0.x; f[1]=r0.y; f[2]=r0.z; f[3]=r0.w;
        f[4]=r1.x; f[5]=r1.y; f[6]=r1.z; f[7]=r1.w;
        f[8]=r2.x; f[9]=r2.y; f[10]=r2.z; f[11]=r2.w;
        f[12]=r3.x; f[13]=r3.y;

        acc += seg_term8(f + 0);   // segment 2tl   : points 6tl..6tl+3
        acc += seg_term8(f + 6);   // segment 2tl+1 : points 6tl+3..6tl+6
    }

    // warp reduce
    #pragma unroll
    for (int off = 16; off > 0; off >>= 1)
        acc += __shfl_down_sync(0xFFFFFFFFu, acc, off);

    __shared__ float warp_sums[256 / 32];
    __shared__ int is_last;
    if (lane == 0) warp_sums[wid] = acc;
    __syncthreads();

    if (wid == 0) {
        float s = (lane < 256 / 32) ? warp_sums[lane] : 0.0f;
        #pragma unroll
        for (int off = 4; off > 0; off >>= 1)
            s += __shfl_down_sync(0xFFFFFFFFu, s, off);
        if (lane == 0) {
            g_partials[blockIdx.x] = s;
            __threadfence();  // once per block (1024 total) -> cheap
            unsigned int prev = atomicAdd(&g_counter, 1u);
            is_last = (prev == (unsigned int)(GRID_BLKS - 1)) ? 1 : 0;
        }
    }
    __syncthreads();

    if (is_last) {
        // 1024 partials / 256 threads = 4 loads each.
        float a = 0.0f;
        #pragma unroll
        for (int j = 0; j < GRID_BLKS / 256; j++)
            a += __ldcg(&g_partials[t + j * 256]);

        #pragma unroll
        for (int off = 16; off > 0; off >>= 1)
            a += __shfl_down_sync(0xFFFFFFFFu, a, off);

        if (lane == 0) warp_sums[wid] = a;
        __syncthreads();

        if (wid == 0) {
            float s = (lane < 256 / 32) ? warp_sums[lane] : 0.0f;
            #pragma unroll
            for (int off = 4; off > 0; off >>= 1)
                s += __shfl_down_sync(0xFFFFFFFFu, s, off);
            if (lane == 0) {
                float scale = decode_scale(scale_p);
                out[0] = s * (scale / ((float)SEGN * (float)P_ROWS));
                g_counter = 0;  // reset for next graph replay
            }
        }
    }
}

extern "C" void kernel_launch(void* const* d_in, const int* in_sizes, int n_in,
                              void* d_out, int out_size) {
    const float* x = (const float*)d_in[0];
    const int* scale_p = (n_in > 1) ? (const int*)d_in[1] : nullptr;
    float* out = (float*)d_out;

    xing_fused_kernel<<<GRID_BLKS, 256>>>(x, scale_p, out);
}